// round 1
// baseline (speedup 1.0000x reference)
#include <cuda_runtime.h>

// Correlation layer: out[b, di*9+dj, y, x] = (1/64) * sum_c f1[b,c,y,x] * f2pad[b,c,y+di,x+dj]
// f2 zero-padded by D=4 on each spatial side.
// Shapes: f1,f2 [4,64,192,448] f32; out [4,81,192,448] f32.

#define DD 4
#define TW 32
#define TH 8
#define CC 64
#define HH 192
#define WW 448
#define BB 4
#define NDISP 81
#define PW (TW + 2*DD)   // 40
#define PH (TH + 2*DD)   // 16

__global__ __launch_bounds__(256, 2)
void corr_kernel(const float* __restrict__ f1,
                 const float* __restrict__ f2,
                 float* __restrict__ out)
{
    __shared__ float tile[2][PH][PW];

    const int tx = threadIdx.x;          // 0..31
    const int ty = threadIdx.y;          // 0..7
    const int tid = ty * TW + tx;        // 0..255
    const int x0 = blockIdx.x * TW;
    const int y0 = blockIdx.y * TH;
    const int b  = blockIdx.z;
    const int x = x0 + tx;
    const int y = y0 + ty;

    const float* f2b = f2 + (size_t)b * CC * HH * WW;
    const float* f1p = f1 + ((size_t)(b * CC) * HH + y) * WW + x;

    float acc[NDISP];
#pragma unroll
    for (int d = 0; d < NDISP; d++) acc[d] = 0.f;

    // cooperative load of one padded f2 channel tile into smem buffer `buf`
    auto load_tile = [&](int c, int buf) {
        const float* src = f2b + (size_t)c * HH * WW;
#pragma unroll
        for (int k = 0; k < 3; k++) {           // ceil(640/256) = 3
            int i = tid + k * 256;
            if (i < PH * PW) {
                int r   = i / PW;
                int col = i - r * PW;
                int yy = y0 - DD + r;
                int xx = x0 - DD + col;
                float v = 0.f;
                if (yy >= 0 && yy < HH && xx >= 0 && xx < WW)
                    v = src[yy * WW + xx];
                tile[buf][r][col] = v;
            }
        }
    };

    load_tile(0, 0);
    __syncthreads();

    for (int c = 0; c < CC; c++) {
        const int cur = c & 1;
        if (c + 1 < CC) load_tile(c + 1, cur ^ 1);

        const float v1 = f1p[(size_t)c * HH * WW];
#pragma unroll
        for (int di = 0; di < 9; di++) {
#pragma unroll
            for (int dj = 0; dj < 9; dj++) {
                acc[di * 9 + dj] += v1 * tile[cur][ty + di][tx + dj];
            }
        }
        __syncthreads();   // cur fully consumed; nxt fully written
    }

    float* outp = out + ((size_t)(b * NDISP) * HH + y) * WW + x;
    const float scale = 1.f / (float)CC;
#pragma unroll
    for (int d = 0; d < NDISP; d++)
        outp[(size_t)d * HH * WW] = acc[d] * scale;
}

extern "C" void kernel_launch(void* const* d_in, const int* in_sizes, int n_in,
                              void* d_out, int out_size)
{
    const float* f1 = (const float*)d_in[0];
    const float* f2 = (const float*)d_in[1];
    float* out = (float*)d_out;

    dim3 grid(WW / TW, HH / TH, BB);   // 14 x 24 x 4 = 1344 CTAs
    dim3 block(TW, TH);                // 256 threads
    corr_kernel<<<grid, block>>>(f1, f2, out);
}

// round 2
// speedup vs baseline: 1.4234x; 1.4234x over previous
#include <cuda_runtime.h>

// Correlation: out[b, di*9+dj, y, x] = (1/64) * sum_c f1[b,c,y,x] * f2pad[b,c,y+di,x+dj]
// f1,f2: [4,64,192,448] f32; out: [4,81,192,448] f32; D=4.
//
// Decomposition: block = (8 x-threads) x (4 y-rows) x (9 di-groups) = 288 threads.
// Each thread owns 4 x-pixels and one di row => 36 accumulators.
// Per channel: window = 12 contiguous floats (3x LDS.128) + f1 quad (1x LDS.128),
// feeding 36 FFMAs => 1.78 B of smem traffic per MAC (was 4 B/MAC).

#define D    4
#define CC   64
#define HH   192
#define WW   448
#define BB   4
#define XT   32
#define YT   4
#define XPT  4
#define NTX  8
#define NDJ  9
#define NDI  9
#define PW   (XT + 2*D)      // 40
#define PH   (YT + 2*D)      // 12
#define CS   4               // channels per stage
#define NSTAGE (CC / CS)     // 16
#define NTHREADS (NTX * YT * NDI)  // 288

__global__ __launch_bounds__(NTHREADS, 3)
void corr_kernel(const float* __restrict__ f1,
                 const float* __restrict__ f2,
                 float* __restrict__ out)
{
    __shared__ float f2s[2][CS][PH][PW];   // 2*4*12*40*4 = 15360 B
    __shared__ float f1s[2][CS][YT][XT];   // 2*4*4*32*4  =  4096 B

    const int tx  = threadIdx.x;   // 0..7
    const int ty  = threadIdx.y;   // 0..3
    const int di  = threadIdx.z;   // 0..8  (one warp per di: 8*4 = 32)
    const int tid = (di * YT + ty) * NTX + tx;

    const int x0 = blockIdx.x * XT;
    const int y0 = blockIdx.y * YT;
    const int b  = blockIdx.z;
    const int y  = y0 + ty;
    const int xp = tx * XPT;       // pixel base inside tile (multiple of 4)

    float acc[NDJ][XPT];
#pragma unroll
    for (int dj = 0; dj < NDJ; dj++)
#pragma unroll
        for (int xx = 0; xx < XPT; xx++) acc[dj][xx] = 0.f;

    const float* f1b0 = f1 + (size_t)b * CC * HH * WW;
    const float* f2b0 = f2 + (size_t)b * CC * HH * WW;

    auto load_stage = [&](int c0, int buf) {
        const float* f2b = f2b0 + (size_t)c0 * HH * WW;
        // f2 padded tile: CS*PH*PW = 1920 floats -> ceil(1920/288)=7 iters
#pragma unroll
        for (int k = 0; k < (CS*PH*PW + NTHREADS - 1) / NTHREADS; k++) {
            int i = tid + k * NTHREADS;
            if (i < CS * PH * PW) {
                int cc  = i / (PH * PW);
                int rem = i - cc * (PH * PW);
                int r   = rem / PW;
                int col = rem - r * PW;
                int gy = y0 - D + r;
                int gx = x0 - D + col;
                float v = 0.f;
                if ((unsigned)gy < HH && (unsigned)gx < WW)
                    v = f2b[cc * (HH * WW) + gy * WW + gx];
                f2s[buf][cc][r][col] = v;
            }
        }
        const float* f1b = f1b0 + (size_t)c0 * HH * WW;
        // f1 tile: CS*YT*XT = 512 floats -> 2 iters
#pragma unroll
        for (int k = 0; k < (CS*YT*XT + NTHREADS - 1) / NTHREADS; k++) {
            int i = tid + k * NTHREADS;
            if (i < CS * YT * XT) {
                int cc  = i / (YT * XT);
                int rem = i - cc * (YT * XT);
                int r   = rem / XT;
                int col = rem - r * XT;
                f1s[buf][cc][r][col] = f1b[cc * (HH * WW) + (y0 + r) * WW + x0 + col];
            }
        }
    };

    load_stage(0, 0);
    __syncthreads();

    for (int s = 0; s < NSTAGE; s++) {
        const int buf = s & 1;
        if (s + 1 < NSTAGE) load_stage((s + 1) * CS, buf ^ 1);

#pragma unroll
        for (int cc = 0; cc < CS; cc++) {
            const float4 v1 = *(const float4*)&f1s[buf][cc][ty][xp];
            float w[12];
            *(float4*)&w[0] = *(const float4*)&f2s[buf][cc][ty + di][xp + 0];
            *(float4*)&w[4] = *(const float4*)&f2s[buf][cc][ty + di][xp + 4];
            *(float4*)&w[8] = *(const float4*)&f2s[buf][cc][ty + di][xp + 8];
#pragma unroll
            for (int dj = 0; dj < NDJ; dj++) {
                acc[dj][0] += v1.x * w[dj + 0];
                acc[dj][1] += v1.y * w[dj + 1];
                acc[dj][2] += v1.z * w[dj + 2];
                acc[dj][3] += v1.w * w[dj + 3];
            }
        }
        __syncthreads();
    }

    const float scale = 1.f / (float)CC;
    float* ob = out + (((size_t)b * (NDI * NDJ) + di * NDJ) * HH + y) * WW + x0 + xp;
#pragma unroll
    for (int dj = 0; dj < NDJ; dj++) {
        float4 o;
        o.x = acc[dj][0] * scale;
        o.y = acc[dj][1] * scale;
        o.z = acc[dj][2] * scale;
        o.w = acc[dj][3] * scale;
        *(float4*)&ob[(size_t)dj * HH * WW] = o;
    }
}

extern "C" void kernel_launch(void* const* d_in, const int* in_sizes, int n_in,
                              void* d_out, int out_size)
{
    const float* f1 = (const float*)d_in[0];
    const float* f2 = (const float*)d_in[1];
    float* out = (float*)d_out;

    dim3 grid(WW / XT, HH / YT, BB);   // 14 x 48 x 4 = 2688 CTAs
    dim3 block(NTX, YT, NDI);          // 288 threads
    corr_kernel<<<grid, block>>>(f1, f2, out);
}

// round 3
// speedup vs baseline: 4.9726x; 3.4936x over previous
#include <cuda_runtime.h>

// Correlation: out[b, di*9+dj, y, x] = (1/64) * sum_c f1[b,c,y,x] * f2pad[b,c,y+di,x+dj]
// f1,f2: [4,64,192,448] f32; out: [4,81,192,448] f32; D=4.
//
// Block: (8 x-threads) x (4 y-rows) x (9 di) = 288 threads; thread owns 4 x-pixels,
// one di row => 36 accumulators. Stage = 4 channels, 4-deep cp.async ring.

#define D    4
#define CC   64
#define HH   192
#define WW   448
#define BB   4
#define XT   32
#define YT   4
#define XPT  4
#define NTX  8
#define NDJ  9
#define NDI  9
#define PW   (XT + 2*D)      // 40
#define PH   (YT + 2*D)      // 12
#define CS   4               // channels per stage
#define NSTAGE (CC / CS)     // 16
#define NTHREADS (NTX * YT * NDI)  // 288
#define RING 4

#define F2_STAGE_FLOATS (CS*PH*PW)     // 1920
#define F1_STAGE_FLOATS (CS*YT*XT)     // 512
#define STAGE_FLOATS    (F2_STAGE_FLOATS + F1_STAGE_FLOATS)  // 2432
#define STAGE_BYTES     (STAGE_FLOATS * 4)                   // 9728

#define NCH_F2 (CS*PH*(PW/4))   // 480 16B chunks
#define NCH_F1 (CS*YT*(XT/4))   // 128 16B chunks
#define NCH    (NCH_F2 + NCH_F1) // 608
#define CSTRIDE_BYTES ((size_t)CS * HH * WW * 4)  // per-stage channel advance

__device__ __forceinline__ void cp_async16(unsigned saddr, const void* gaddr, int sz) {
    asm volatile("cp.async.cg.shared.global [%0], [%1], 16, %2;"
                 :: "r"(saddr), "l"(gaddr), "r"(sz));
}

__global__ __launch_bounds__(NTHREADS, 3)
void corr_kernel(const float* __restrict__ f1,
                 const float* __restrict__ f2,
                 float* __restrict__ out)
{
    __shared__ float smem[RING * STAGE_FLOATS];   // 38912 B

    const int tx  = threadIdx.x;   // 0..7
    const int ty  = threadIdx.y;   // 0..3
    const int di  = threadIdx.z;   // 0..8
    const int tid = (di * YT + ty) * NTX + tx;

    const int x0 = blockIdx.x * XT;
    const int y0 = blockIdx.y * YT;
    const int b  = blockIdx.z;
    const int y  = y0 + ty;
    const int xp = tx * XPT;

    const float* f1b0 = f1 + (size_t)b * CC * HH * WW;
    const float* f2b0 = f2 + (size_t)b * CC * HH * WW;

    const unsigned sbase = (unsigned)__cvta_generic_to_shared(smem);

    // ---- precompute this thread's load chunks (2 for all, a 3rd for tid<32) ----
    const char* ckp[2];
    unsigned    cks[2];
    int         ckz[2];
#pragma unroll
    for (int k = 0; k < 2; k++) {
        const int c = tid + k * NTHREADS;   // < 608 always
        if (c < NCH_F2) {
            const int cc = c / (PH * (PW/4));
            const int rem = c - cc * (PH * (PW/4));
            const int r  = rem / (PW/4);
            const int h  = rem - r * (PW/4);
            const int gy  = y0 - D + r;
            const int gxf = x0 - D + h * 4;
            const bool ok = ((unsigned)gy < HH) && ((unsigned)gxf < WW);
            ckp[k] = (const char*)(f2b0 + (size_t)cc * HH * WW
                                  + (ok ? ((size_t)gy * WW + gxf) : 0));
            ckz[k] = ok ? 16 : 0;
            cks[k] = ((cc * PH + r) * PW + h * 4) * 4;
        } else {
            const int c2 = c - NCH_F2;
            const int cc = c2 / (YT * (XT/4));
            const int rem = c2 - cc * (YT * (XT/4));
            const int r  = rem / (XT/4);
            const int h  = rem - r * (XT/4);
            ckp[k] = (const char*)(f1b0 + (size_t)cc * HH * WW
                                  + (size_t)(y0 + r) * WW + x0 + h * 4);
            ckz[k] = 16;
            cks[k] = F2_STAGE_FLOATS * 4 + ((cc * YT + r) * XT + h * 4) * 4;
        }
    }
    // third chunk (f2 region, only threads 0..31): c = tid + 576 in [576, 608)
    const bool has3 = (tid < NCH - 2 * NTHREADS);
    const char* ck3p = nullptr; unsigned ck3s = 0; int ck3z = 0;
    if (has3) {
        const int c = tid + 2 * NTHREADS;     // 576..607, all < 480? no: 576 >= 480 -> f1 region
        const int c2 = c - NCH_F2;            // 96..127
        const int cc = c2 / (YT * (XT/4));
        const int rem = c2 - cc * (YT * (XT/4));
        const int r  = rem / (XT/4);
        const int h  = rem - r * (XT/4);
        ck3p = (const char*)(f1b0 + (size_t)cc * HH * WW
                             + (size_t)(y0 + r) * WW + x0 + h * 4);
        ck3z = 16;
        ck3s = F2_STAGE_FLOATS * 4 + ((cc * YT + r) * XT + h * 4) * 4;
    }

    auto prefetch = [&](int s) {
        if (s < NSTAGE) {
            const size_t gadd = (size_t)s * CSTRIDE_BYTES;
            const unsigned sb = sbase + (s & (RING - 1)) * STAGE_BYTES;
            cp_async16(sb + cks[0], ckp[0] + gadd, ckz[0]);
            cp_async16(sb + cks[1], ckp[1] + gadd, ckz[1]);
            if (has3) cp_async16(sb + ck3s, ck3p + gadd, ck3z);
        }
        asm volatile("cp.async.commit_group;" ::: "memory");
    };

    float acc[NDJ][XPT];
#pragma unroll
    for (int dj = 0; dj < NDJ; dj++)
#pragma unroll
        for (int xx = 0; xx < XPT; xx++) acc[dj][xx] = 0.f;

    prefetch(0);
    prefetch(1);
    prefetch(2);

#pragma unroll 4
    for (int s = 0; s < NSTAGE; s++) {
        asm volatile("cp.async.wait_group 2;" ::: "memory");
        __syncthreads();

        const float* f2t = smem + (s & (RING - 1)) * STAGE_FLOATS;
        const float* f1t = f2t + F2_STAGE_FLOATS;

#pragma unroll
        for (int cc = 0; cc < CS; cc++) {
            const float4 v1 = *(const float4*)&f1t[(cc * YT + ty) * XT + xp];
            const float* wrow = &f2t[(cc * PH + ty + di) * PW + xp];
            float w[12];
            *(float4*)&w[0] = *(const float4*)&wrow[0];
            *(float4*)&w[4] = *(const float4*)&wrow[4];
            *(float4*)&w[8] = *(const float4*)&wrow[8];
#pragma unroll
            for (int dj = 0; dj < NDJ; dj++) {
                acc[dj][0] += v1.x * w[dj + 0];
                acc[dj][1] += v1.y * w[dj + 1];
                acc[dj][2] += v1.z * w[dj + 2];
                acc[dj][3] += v1.w * w[dj + 3];
            }
        }
        // One barrier per stage: next iteration's prefetch overwrites buf (s-1)&3,
        // which every thread finished before passing THIS iteration's barrier.
        prefetch(s + 3);
    }

    const float scale = 1.f / (float)CC;
    float* ob = out + (((size_t)b * (NDI * NDJ) + di * NDJ) * HH + y) * WW + x0 + xp;
#pragma unroll
    for (int dj = 0; dj < NDJ; dj++) {
        float4 o;
        o.x = acc[dj][0] * scale;
        o.y = acc[dj][1] * scale;
        o.z = acc[dj][2] * scale;
        o.w = acc[dj][3] * scale;
        *(float4*)&ob[(size_t)dj * HH * WW] = o;
    }
}

extern "C" void kernel_launch(void* const* d_in, const int* in_sizes, int n_in,
                              void* d_out, int out_size)
{
    const float* f1 = (const float*)d_in[0];
    const float* f2 = (const float*)d_in[1];
    float* out = (float*)d_out;

    dim3 grid(WW / XT, HH / YT, BB);   // 14 x 48 x 4 = 2688 CTAs
    dim3 block(NTX, YT, NDI);          // 288 threads
    corr_kernel<<<grid, block>>>(f1, f2, out);
}